// round 13
// baseline (speedup 1.0000x reference)
#include <cuda_runtime.h>
#include <math.h>
#include <stdint.h>

#define Bn 128
#define Tn 1024
#define Hn 512

// Packed dual-FMA: acc(f32x2) += a(f32x2) * b(f32x2), IEEE fp32 per lane.
#define FMA2(acc, a, b) \
    asm("fma.rn.f32x2 %0, %1, %2, %0;" : "+l"(acc) : "l"(a), "l"(b))
#define DUP2(d, f) \
    asm("mov.b64 %0, {%1, %1};" : "=l"(d) : "f"(f))
#define PACK2(d, lo, hi) \
    asm("mov.b64 %0, {%1, %2};" : "=l"(d) : "f"(lo), "f"(hi))

union UF2 { unsigned long long u; float2 f; };

// Per-(rowgroup, step, colgroup) flags: one 32B sector per (rg,t).
__device__ unsigned g_flag[16 * 1024 * 8];

__global__ void zero_flag() {
    int i = blockIdx.x * blockDim.x + threadIdx.x;
    if (i < 16 * 1024 * 8) g_flag[i] = 0u;
}

__device__ __forceinline__ unsigned ld_acq(const unsigned* p) {
    unsigned v;
    asm volatile("ld.acquire.gpu.global.u32 %0, [%1];" : "=r"(v) : "l"(p));
    return v;
}
__device__ __forceinline__ void st_rel(unsigned* p, unsigned v) {
    asm volatile("st.release.gpu.global.u32 [%0], %1;" :: "l"(p), "r"(v) : "memory");
}

// ---------------------------------------------------------------------------
// Phase 1: pre[t][b][:] = X[b][t][:] @ Wx + bias  (R9/R10's proven version)
// BM=128, BN=128, BK=16, 256 threads, 8x8/thread, fma.rn.f32x2 inner loop.
// ---------------------------------------------------------------------------
__global__ __launch_bounds__(256) void gemm_xw(
    const float* __restrict__ X,    // [B*T, H] rows r = b*T + t
    const float* __restrict__ Wx,   // [H, H]
    const float* __restrict__ bias, // [H]
    float* __restrict__ out)        // [T, B, H]
{
    __shared__ float As[16][132];   // [k][row]
    __shared__ float Bs[16][132];   // [k][col]

    const int bm0 = blockIdx.y * 128;
    const int bn0 = blockIdx.x * 128;
    const int tid = threadIdx.x;
    const int tr  = (tid >> 4) << 3;
    const int tc  = (tid & 15) << 3;

    unsigned long long acc2[8][4];
#pragma unroll
    for (int i = 0; i < 8; i++)
#pragma unroll
        for (int j = 0; j < 4; j++) acc2[i][j] = 0ull;

    for (int k0 = 0; k0 < Hn; k0 += 16) {
#pragma unroll
        for (int v = 0; v < 2; v++) {
            int f   = tid + (v << 8);
            int row = f >> 2;
            int kk  = (f & 3) << 2;
            float4 a = *(const float4*)(X + (size_t)(bm0 + row) * Hn + k0 + kk);
            As[kk + 0][row] = a.x;
            As[kk + 1][row] = a.y;
            As[kk + 2][row] = a.z;
            As[kk + 3][row] = a.w;
        }
#pragma unroll
        for (int v = 0; v < 2; v++) {
            int f   = tid + (v << 8);
            int kk  = f >> 5;
            int col = (f & 31) << 2;
            *(float4*)&Bs[kk][col] =
                *(const float4*)(Wx + (size_t)(k0 + kk) * Hn + bn0 + col);
        }
        __syncthreads();

#pragma unroll
        for (int kk = 0; kk < 16; kk++) {
            float4 a0 = *(const float4*)&As[kk][tr];
            float4 a1 = *(const float4*)&As[kk][tr + 4];
            ulonglong2 bv0 = *(const ulonglong2*)&Bs[kk][tc];
            ulonglong2 bv1 = *(const ulonglong2*)&Bs[kk][tc + 4];
            float av[8] = {a0.x, a0.y, a0.z, a0.w, a1.x, a1.y, a1.z, a1.w};
#pragma unroll
            for (int i = 0; i < 8; i++) {
                unsigned long long d;
                DUP2(d, av[i]);
                FMA2(acc2[i][0], d, bv0.x);
                FMA2(acc2[i][1], d, bv0.y);
                FMA2(acc2[i][2], d, bv1.x);
                FMA2(acc2[i][3], d, bv1.y);
            }
        }
        __syncthreads();
    }

    float4 bb0 = *(const float4*)(bias + bn0 + tc);
    float4 bb1 = *(const float4*)(bias + bn0 + tc + 4);
#pragma unroll
    for (int i = 0; i < 8; i++) {
        int m = bm0 + tr + i;
        int b = m >> 10;
        int t = m & 1023;
        UF2 q0, q1, q2, q3;
        q0.u = acc2[i][0];
        q1.u = acc2[i][1];
        q2.u = acc2[i][2];
        q3.u = acc2[i][3];
        float4 o0, o1;
        o0.x = q0.f.x + bb0.x;
        o0.y = q0.f.y + bb0.y;
        o0.z = q1.f.x + bb0.z;
        o0.w = q1.f.y + bb0.w;
        o1.x = q2.f.x + bb1.x;
        o1.y = q2.f.y + bb1.y;
        o1.z = q3.f.x + bb1.z;
        o1.w = q3.f.y + bb1.w;
        float* dst = out + ((size_t)t * Bn + b) * Hn + bn0 + tc;
        *(float4*)(dst)     = o0;
        *(float4*)(dst + 4) = o1;
    }
}

// ---------------------------------------------------------------------------
// Phase 2: persistent RNN, per-PRODUCER flags.
// 128 CTAs = 16 rowgroups x 8 colgroups, 512 threads.
// Warp w consumes k [32w,32w+32) = part of colgroup (w>>1)'s chunk, so it
// acquire-polls ONLY that producer's flag, then stages + FMAs immediately:
// early warps compute while late producers finish (de-convoyed).
// Producer: outputs stcg -> syncthreads -> tid0 threadfence + st.release flag.
// Two syncthreads/step protect Ps; Sw is warp-private.
// ---------------------------------------------------------------------------
#define SWSTR 36                          // per-warp state row stride (floats)
#define SW_FLOATS (8 * SWSTR)             // 288 per warp
#define PSQ 544                           // partials per k-chunk (8 x 68)
#define RNN_SMEM_BYTES ((16 * SW_FLOATS + 16 * PSQ) * 4)   // 53248

__global__ __launch_bounds__(512) void rnn_steps(
    const float* __restrict__ state0,  // [B, H]
    const float* __restrict__ Wh,      // [H, H]
    float* __restrict__ out)           // [T, B, H] (holds pre on entry)
{
    extern __shared__ float sm[];
    float* SwA = sm;                      // [16][8][36] per-warp state chunks
    float* Ps  = sm + 16 * SW_FLOATS;     // [16][8][68] k-chunk partials

    const int tid  = threadIdx.x;
    const int w    = tid >> 5;            // warp = k-chunk [32w, 32w+32)
    const int lane = tid & 31;
    const int cg   = blockIdx.x & 7;
    const int rg   = blockIdx.x >> 3;
    const int c0   = cg * 64;
    const int r0   = rg * 8;

    // weights: thread covers cols {gc, gc+1}, k in [32w, 32w+32)
    const int gc = c0 + lane * 2;
    unsigned long long w2a[16], w2b[16];
    {
        const float* wb = Wh + (size_t)(w * 32) * Hn + gc;
#pragma unroll
        for (int j = 0; j < 16; j++) {
            float a0 = wb[(2 * j) * Hn];
            float a1 = wb[(2 * j + 1) * Hn];
            float b0 = wb[(2 * j) * Hn + 1];
            float b1 = wb[(2 * j + 1) * Hn + 1];
            PACK2(w2a[j], a0, a1);
            PACK2(w2b[j], b0, b1);
        }
    }

    // epilogue mapping: one output element per thread
    const int rr = tid >> 6;              // 0..7
    const int cc = tid & 63;              // 0..63
    float* opbase = out + (size_t)(r0 + rr) * Hn + c0 + cc;

    // self-staging mapping: warp w loads rows 0..7 x k[32w,32w+32)
    const int sr  = lane >> 3;            // 0..3  (and +4 on second load)
    const int sk4 = (lane & 7) << 2;      // 0..28

    float* Sw = SwA + w * SW_FLOATS;
    unsigned* flags = &g_flag[rg * 1024 * 8];   // [t][cg]
    const int prod = w >> 1;              // producer colgroup of my k-chunk

    for (int t = 0; t < Tn; t++) {
        float* op = opbase + (size_t)t * (Bn * Hn);
        float pre = __ldcg(op);           // pre-activation (written in phase 1)

        // ---- wait ONLY for my producer's step t-1 chunk ----
        if (t > 0) {
            const unsigned* f = &flags[(t - 1) * 8 + prod];
            while (ld_acq(f) == 0u) { }
        }

        // ---- self-stage own k-chunk ----
        const float* prev = (t == 0) ? state0
                                     : (out + (size_t)(t - 1) * (Bn * Hn));
        {
            const float* pk = prev + (size_t)r0 * Hn + w * 32 + sk4;
            float4 v0 = __ldcg((const float4*)(pk + (size_t)sr * Hn));
            float4 v1 = __ldcg((const float4*)(pk + (size_t)(sr + 4) * Hn));
            *(float4*)(Sw + sr * SWSTR + sk4)       = v0;
            *(float4*)(Sw + (sr + 4) * SWSTR + sk4) = v1;
        }
        __syncwarp();

        // ---- FMA: 8 rows x 2 cols x 32 k per thread ----
        unsigned long long acc[8][2];
#pragma unroll
        for (int r = 0; r < 8; r++) { acc[r][0] = 0ull; acc[r][1] = 0ull; }
#pragma unroll
        for (int jj = 0; jj < 8; jj++) {
            const int k = jj * 4;
#pragma unroll
            for (int r = 0; r < 8; r++) {
                ulonglong2 sv = *(const ulonglong2*)(Sw + r * SWSTR + k);
                FMA2(acc[r][0], sv.x, w2a[2 * jj]);
                FMA2(acc[r][0], sv.y, w2a[2 * jj + 1]);
                FMA2(acc[r][1], sv.x, w2b[2 * jj]);
                FMA2(acc[r][1], sv.y, w2b[2 * jj + 1]);
            }
        }

        // ---- partials ----
        {
            float* pb = Ps + w * PSQ + lane * 2;
#pragma unroll
            for (int r = 0; r < 8; r++) {
                UF2 u0, u1;
                u0.u = acc[r][0];
                u1.u = acc[r][1];
                float2 p;
                p.x = u0.f.x + u0.f.y;
                p.y = u1.f.x + u1.f.y;
                *(float2*)(pb + r * 68) = p;
            }
        }
        __syncthreads();                  // partials ready

        // ---- reduce 16 k-chunks + tanh + publish value ----
        {
            const float* pp = Ps + rr * 68 + cc;
            float s = 0.0f;
#pragma unroll
            for (int q = 0; q < 16; q++) s += pp[q * PSQ];
            __stcg(op, tanhf(pre + s));
        }
        __syncthreads();                  // stores issued + Ps safe to reuse

        // ---- publish own chunk flag ----
        if (t != Tn - 1 && tid == 0) {
            __threadfence();              // drain CTA's stcg to L2
            st_rel(&flags[t * 8 + cg], 1u);
        }
    }
}

extern "C" void kernel_launch(void* const* d_in, const int* in_sizes, int n_in,
                              void* d_out, int out_size)
{
    const float* X    = (const float*)d_in[0];  // inputs_tensor [B,T,H]
    const float* S0   = (const float*)d_in[1];  // state_tensor  [1,B,H]
    const float* Wx   = (const float*)d_in[2];  // [H,H]
    const float* Wh   = (const float*)d_in[3];  // [H,H]
    const float* bias = (const float*)d_in[4];  // [H]
    float* out = (float*)d_out;                 // [T,B,H]

    (void)in_sizes; (void)n_in; (void)out_size;

    cudaFuncSetAttribute(rnn_steps,
                         cudaFuncAttributeMaxDynamicSharedMemorySize,
                         RNN_SMEM_BYTES);

    zero_flag<<<256, 512>>>();

    dim3 g1(Hn / 128, (Bn * Tn) / 128);  // (4, 1024)
    gemm_xw<<<g1, 256>>>(X, Wx, bias, out);

    rnn_steps<<<128, 512, RNN_SMEM_BYTES>>>(S0, Wh, out);
}

// round 14
// speedup vs baseline: 1.0935x; 1.0935x over previous
#include <cuda_runtime.h>
#include <math.h>
#include <stdint.h>

#define Bn 128
#define Tn 1024
#define Hn 512

// Packed dual-FMA: acc(f32x2) += a(f32x2) * b(f32x2), IEEE fp32 per lane.
#define FMA2(acc, a, b) \
    asm("fma.rn.f32x2 %0, %1, %2, %0;" : "+l"(acc) : "l"(a), "l"(b))
#define DUP2(d, f) \
    asm("mov.b64 %0, {%1, %1};" : "=l"(d) : "f"(f))

union UF2 { unsigned long long u; float2 f; };

__device__ unsigned g_cnt[16 * 1024];   // [rg][t] CTA arrivals (target 8)
__device__ float4 g_WhP[65536];         // packed Wh, 1 MB

__global__ void zero_cnt() {
    int i = blockIdx.x * blockDim.x + threadIdx.x;
    if (i < 16 * 1024) g_cnt[i] = 0u;
}

// Pack Wh[k][c] -> [cg][w16][jj8][half2][lane32] float4 = Wh[k..k+3][c]
// with k = 32w + 4jj, c = 64cg + 32half + lane. Consumer LDS.128 is
// conflict-free (consecutive lanes -> consecutive 16B).
__global__ void pack_wh(const float* __restrict__ Wh) {
    int i    = blockIdx.x * 256 + threadIdx.x;   // 0..65535
    int l    = i & 31;
    int half = (i >> 5) & 1;
    int jj   = (i >> 6) & 7;
    int w    = (i >> 9) & 15;
    int cg   = i >> 13;
    int k    = w * 32 + jj * 4;
    int c    = cg * 64 + half * 32 + l;
    float4 v;
    v.x = Wh[(size_t)(k + 0) * Hn + c];
    v.y = Wh[(size_t)(k + 1) * Hn + c];
    v.z = Wh[(size_t)(k + 2) * Hn + c];
    v.w = Wh[(size_t)(k + 3) * Hn + c];
    g_WhP[i] = v;
}

__device__ __forceinline__ unsigned ld_acq(const unsigned* p) {
    unsigned v;
    asm volatile("ld.acquire.gpu.global.u32 %0, [%1];" : "=r"(v) : "l"(p));
    return v;
}

// ---------------------------------------------------------------------------
// Phase 1: pre[t][b][:] = X[b][t][:] @ Wx + bias  (R10's proven version)
// BM=128, BN=128, BK=16, 256 threads, 8x8/thread, fma.rn.f32x2 inner loop.
// ---------------------------------------------------------------------------
__global__ __launch_bounds__(256) void gemm_xw(
    const float* __restrict__ X,    // [B*T, H] rows r = b*T + t
    const float* __restrict__ Wx,   // [H, H]
    const float* __restrict__ bias, // [H]
    float* __restrict__ out)        // [T, B, H]
{
    __shared__ float As[16][132];   // [k][row]
    __shared__ float Bs[16][132];   // [k][col]

    const int bm0 = blockIdx.y * 128;
    const int bn0 = blockIdx.x * 128;
    const int tid = threadIdx.x;
    const int tr  = (tid >> 4) << 3;
    const int tc  = (tid & 15) << 3;

    unsigned long long acc2[8][4];
#pragma unroll
    for (int i = 0; i < 8; i++)
#pragma unroll
        for (int j = 0; j < 4; j++) acc2[i][j] = 0ull;

    for (int k0 = 0; k0 < Hn; k0 += 16) {
#pragma unroll
        for (int v = 0; v < 2; v++) {
            int f   = tid + (v << 8);
            int row = f >> 2;
            int kk  = (f & 3) << 2;
            float4 a = *(const float4*)(X + (size_t)(bm0 + row) * Hn + k0 + kk);
            As[kk + 0][row] = a.x;
            As[kk + 1][row] = a.y;
            As[kk + 2][row] = a.z;
            As[kk + 3][row] = a.w;
        }
#pragma unroll
        for (int v = 0; v < 2; v++) {
            int f   = tid + (v << 8);
            int kk  = f >> 5;
            int col = (f & 31) << 2;
            *(float4*)&Bs[kk][col] =
                *(const float4*)(Wx + (size_t)(k0 + kk) * Hn + bn0 + col);
        }
        __syncthreads();

#pragma unroll
        for (int kk = 0; kk < 16; kk++) {
            float4 a0 = *(const float4*)&As[kk][tr];
            float4 a1 = *(const float4*)&As[kk][tr + 4];
            ulonglong2 bv0 = *(const ulonglong2*)&Bs[kk][tc];
            ulonglong2 bv1 = *(const ulonglong2*)&Bs[kk][tc + 4];
            float av[8] = {a0.x, a0.y, a0.z, a0.w, a1.x, a1.y, a1.z, a1.w};
#pragma unroll
            for (int i = 0; i < 8; i++) {
                unsigned long long d;
                DUP2(d, av[i]);
                FMA2(acc2[i][0], d, bv0.x);
                FMA2(acc2[i][1], d, bv0.y);
                FMA2(acc2[i][2], d, bv1.x);
                FMA2(acc2[i][3], d, bv1.y);
            }
        }
        __syncthreads();
    }

    float4 bb0 = *(const float4*)(bias + bn0 + tc);
    float4 bb1 = *(const float4*)(bias + bn0 + tc + 4);
#pragma unroll
    for (int i = 0; i < 8; i++) {
        int m = bm0 + tr + i;
        int b = m >> 10;
        int t = m & 1023;
        UF2 q0, q1, q2, q3;
        q0.u = acc2[i][0];
        q1.u = acc2[i][1];
        q2.u = acc2[i][2];
        q3.u = acc2[i][3];
        float4 o0, o1;
        o0.x = q0.f.x + bb0.x;
        o0.y = q0.f.y + bb0.y;
        o0.z = q1.f.x + bb0.z;
        o0.w = q1.f.y + bb0.w;
        o1.x = q2.f.x + bb1.x;
        o1.y = q2.f.y + bb1.y;
        o1.z = q3.f.x + bb1.z;
        o1.w = q3.f.y + bb1.w;
        float* dst = out + ((size_t)t * Bn + b) * Hn + bn0 + tc;
        *(float4*)(dst)     = o0;
        *(float4*)(dst + 4) = o1;
    }
}

// ---------------------------------------------------------------------------
// Phase 2: persistent RNN — R10 skeleton, weights from SMEM (no reg spill,
// no per-step weight LDGs). Warp w: k-chunk [32w,32w+32), thread covers
// cols {c0+l, c0+32+l}. Inner loop per jj: 2 conflict-free LDS.128 weight
// loads + 8 broadcast state LDS.128 + 16 FMA2.
// ---------------------------------------------------------------------------
#define SWSTR 36                          // per-warp state row stride (floats)
#define SW_FLOATS (8 * SWSTR)             // 288 per warp
#define PSQ 544                           // partials per k-chunk (8 x 68)
#define WHS_F4 8192                       // 128 KB packed Wh slice (float4)
#define RNN_SMEM_BYTES (WHS_F4 * 16 + (16 * SW_FLOATS + 16 * PSQ) * 4) // 184320

__global__ __launch_bounds__(512) void rnn_steps(
    const float* __restrict__ state0,  // [B, H]
    float* __restrict__ out)           // [T, B, H] (holds pre on entry)
{
    extern __shared__ float sm[];
    float4* Whs = (float4*)sm;            // [8192] packed Wh slice
    float* SwA  = sm + WHS_F4 * 4;        // [16][8][36] per-warp state chunks
    float* Ps   = SwA + 16 * SW_FLOATS;   // [16][8][68] k-chunk partials

    const int tid  = threadIdx.x;
    const int w    = tid >> 5;            // warp = k-chunk [32w, 32w+32)
    const int lane = tid & 31;
    const int cg   = blockIdx.x & 7;
    const int rg   = blockIdx.x >> 3;
    const int c0   = cg * 64;
    const int r0   = rg * 8;

    // ---- one-time: packed Wh slice -> smem (16 float4 per thread) ----
    {
        const float4* src = g_WhP + (size_t)cg * WHS_F4;
#pragma unroll
        for (int i = 0; i < 16; i++)
            Whs[tid + i * 512] = src[tid + i * 512];
    }

    // epilogue mapping: one output element per thread
    const int rr = tid >> 6;              // 0..7
    const int cc = tid & 63;              // 0..63
    float* opbase = out + (size_t)(r0 + rr) * Hn + c0 + cc;

    // self-staging mapping: warp w loads rows 0..7 x k[32w,32w+32)
    const int sr  = lane >> 3;            // 0..3  (and +4 on second load)
    const int sk4 = (lane & 7) << 2;      // 0..28

    float* Sw = SwA + w * SW_FLOATS;
    const float4* whbase = Whs + w * 512; // [jj8][half2][lane32]
    unsigned* cnt = &g_cnt[rg * 1024];

    __syncthreads();                      // Whs ready

    for (int t = 0; t < Tn; t++) {
        float* op = opbase + (size_t)t * (Bn * Hn);
        float pre = __ldcg(op);           // pre-activation (written in phase 1)

        // ---- acquire-poll peers' step t-1 (every thread; self-releasing) ----
        if (t > 0) {
            while (ld_acq(&cnt[t - 1]) < 8u) { }
        }

        // ---- self-stage own k-chunk ----
        const float* prev = (t == 0) ? state0
                                     : (out + (size_t)(t - 1) * (Bn * Hn));
        {
            const float* pk = prev + (size_t)r0 * Hn + w * 32 + sk4;
            float4 v0 = __ldcg((const float4*)(pk + (size_t)sr * Hn));
            float4 v1 = __ldcg((const float4*)(pk + (size_t)(sr + 4) * Hn));
            *(float4*)(Sw + sr * SWSTR + sk4)       = v0;
            *(float4*)(Sw + (sr + 4) * SWSTR + sk4) = v1;
        }
        __syncwarp();

        // ---- FMA: 8 rows x 2 cols x 32 k per thread, weights from smem ----
        unsigned long long acc[8][2];
#pragma unroll
        for (int r = 0; r < 8; r++) { acc[r][0] = 0ull; acc[r][1] = 0ull; }
#pragma unroll
        for (int jj = 0; jj < 8; jj++) {
            ulonglong2 wh0 = *(const ulonglong2*)(whbase + jj * 64 + lane);
            ulonglong2 wh1 = *(const ulonglong2*)(whbase + jj * 64 + 32 + lane);
            const int k = jj * 4;
#pragma unroll
            for (int r = 0; r < 8; r++) {
                ulonglong2 sv = *(const ulonglong2*)(Sw + r * SWSTR + k);
                FMA2(acc[r][0], sv.x, wh0.x);
                FMA2(acc[r][0], sv.y, wh0.y);
                FMA2(acc[r][1], sv.x, wh1.x);
                FMA2(acc[r][1], sv.y, wh1.y);
            }
        }

        // ---- partials: cols l and l+32 per row ----
        {
            float* pb = Ps + w * PSQ;
#pragma unroll
            for (int r = 0; r < 8; r++) {
                UF2 u0, u1;
                u0.u = acc[r][0];
                u1.u = acc[r][1];
                pb[r * 68 + lane]      = u0.f.x + u0.f.y;
                pb[r * 68 + 32 + lane] = u1.f.x + u1.f.y;
            }
        }
        __syncthreads();                  // partials ready

        // ---- reduce 16 k-chunks + tanh + publish value ----
        {
            const float* pp = Ps + rr * 68 + cc;
            float s = 0.0f;
#pragma unroll
            for (int q = 0; q < 16; q++) s += pp[q * PSQ];
            __stcg(op, tanhf(pre + s));
        }
        __syncthreads();                  // stores issued + Ps safe to reuse

        if (t != Tn - 1 && tid == 0) {
            __threadfence();              // publish chunk before arrive
            atomicAdd(&cnt[t], 1u);
        }
    }
}

extern "C" void kernel_launch(void* const* d_in, const int* in_sizes, int n_in,
                              void* d_out, int out_size)
{
    const float* X    = (const float*)d_in[0];  // inputs_tensor [B,T,H]
    const float* S0   = (const float*)d_in[1];  // state_tensor  [1,B,H]
    const float* Wx   = (const float*)d_in[2];  // [H,H]
    const float* Wh   = (const float*)d_in[3];  // [H,H]
    const float* bias = (const float*)d_in[4];  // [H]
    float* out = (float*)d_out;                 // [T,B,H]

    (void)in_sizes; (void)n_in; (void)out_size;

    cudaFuncSetAttribute(rnn_steps,
                         cudaFuncAttributeMaxDynamicSharedMemorySize,
                         RNN_SMEM_BYTES);

    zero_cnt<<<32, 512>>>();
    pack_wh<<<256, 256>>>(Wh);

    dim3 g1(Hn / 128, (Bn * Tn) / 128);  // (4, 1024)
    gemm_xw<<<g1, 256>>>(X, Wx, bias, out);

    rnn_steps<<<128, 512, RNN_SMEM_BYTES>>>(S0, out);
}

// round 16
// speedup vs baseline: 1.4070x; 1.2867x over previous
#include <cuda_runtime.h>
#include <cuda_bf16.h>
#include <math.h>
#include <stdint.h>

#define Bn 128
#define Tn 1024
#define Hn 512

// Packed dual-FMA: acc(f32x2) += a(f32x2) * b(f32x2), IEEE fp32 per lane.
#define FMA2(acc, a, b) \
    asm("fma.rn.f32x2 %0, %1, %2, %0;" : "+l"(acc) : "l"(a), "l"(b))
#define PACK2(d, lo, hi) \
    asm("mov.b64 %0, {%1, %2};" : "=l"(d) : "f"(lo), "f"(hi))

union UF2 { unsigned long long u; float2 f; };

__device__ unsigned g_cnt[16 * 1024];   // [rg][t] CTA arrivals (target 8)

// bf16 two-term splits, packed once per launch.
__device__ __nv_bfloat16 g_Xhi[(size_t)Bn * Tn * Hn];   // 128 MiB
__device__ __nv_bfloat16 g_Xlo[(size_t)Bn * Tn * Hn];   // 128 MiB
__device__ __nv_bfloat16 g_Wth[Hn * Hn];                // Wx^T [n][k], hi
__device__ __nv_bfloat16 g_Wtl[Hn * Hn];                // Wx^T [n][k], lo

__global__ void zero_cnt() {
    int i = blockIdx.x * blockDim.x + threadIdx.x;
    if (i < 16 * 1024) g_cnt[i] = 0u;
}

__device__ __forceinline__ unsigned ld_acq(const unsigned* p) {
    unsigned v;
    asm volatile("ld.acquire.gpu.global.u32 %0, [%1];" : "=r"(v) : "l"(p));
    return v;
}

// ---- pack kernels ---------------------------------------------------------
__global__ __launch_bounds__(256) void pack_x(const float* __restrict__ X) {
    size_t i = ((size_t)blockIdx.x * 256 + threadIdx.x) * 4;
    float4 v = *(const float4*)(X + i);
    __nv_bfloat16 h0 = __float2bfloat16(v.x);
    __nv_bfloat16 h1 = __float2bfloat16(v.y);
    __nv_bfloat16 h2 = __float2bfloat16(v.z);
    __nv_bfloat16 h3 = __float2bfloat16(v.w);
    __nv_bfloat162 hp0(h0, h1), hp1(h2, h3);
    *(__nv_bfloat162*)(g_Xhi + i)     = hp0;
    *(__nv_bfloat162*)(g_Xhi + i + 2) = hp1;
    __nv_bfloat16 l0 = __float2bfloat16(v.x - __bfloat162float(h0));
    __nv_bfloat16 l1 = __float2bfloat16(v.y - __bfloat162float(h1));
    __nv_bfloat16 l2 = __float2bfloat16(v.z - __bfloat162float(h2));
    __nv_bfloat16 l3 = __float2bfloat16(v.w - __bfloat162float(h3));
    __nv_bfloat162 lp0(l0, l1), lp1(l2, l3);
    *(__nv_bfloat162*)(g_Xlo + i)     = lp0;
    *(__nv_bfloat162*)(g_Xlo + i + 2) = lp1;
}

__global__ __launch_bounds__(256) void pack_wt(const float* __restrict__ Wx) {
    int i = blockIdx.x * 256 + threadIdx.x;   // i = n*512 + k
    int n = i >> 9, k = i & 511;
    float v = Wx[(size_t)k * Hn + n];
    __nv_bfloat16 h = __float2bfloat16(v);
    g_Wth[i] = h;
    g_Wtl[i] = __float2bfloat16(v - __bfloat162float(h));
}

// ---- HMMA helpers ---------------------------------------------------------
#define MMA_BF16(d, a, b) \
    asm volatile("mma.sync.aligned.m16n8k16.row.col.f32.bf16.bf16.f32 " \
        "{%0,%1,%2,%3}, {%4,%5,%6,%7}, {%8,%9}, {%0,%1,%2,%3};" \
        : "+f"((d)[0]), "+f"((d)[1]), "+f"((d)[2]), "+f"((d)[3]) \
        : "r"((a)[0]), "r"((a)[1]), "r"((a)[2]), "r"((a)[3]), \
          "r"((b)[0]), "r"((b)[1]))

__device__ __forceinline__ void cp16(uint32_t s, const void* g) {
    asm volatile("cp.async.cg.shared.global [%0], [%1], 16;" :: "r"(s), "l"(g));
}
#define CP_COMMIT() asm volatile("cp.async.commit_group;" ::: "memory")
#define CP_WAIT(n)  asm volatile("cp.async.wait_group %0;" :: "n"(n) : "memory")

// ---------------------------------------------------------------------------
// Phase 1: pre = X @ Wx + bias via mma.sync bf16 3-term split.
// Tile 128x128, 256 threads (8 warps: wm = wid&3 -> 32 m-rows, wn = wid>>2
// -> 64 n-cols). K in 8 chunks of 64, 2-stage cp.async pipeline.
// smem rows padded to 144B: frag LDS bank = (4*row + tig) mod 32 -> no conflicts.
// ---------------------------------------------------------------------------
#define KC 64
#define KPAD 72                         // bf16 elems per row (144 B)
#define ATILE (128 * KPAD)              // 9216 bf16 = 18 KB per array
#define STAGE_ELEMS (4 * ATILE)         // Ahi, Alo, Bhi, Blo
#define GEMM_SMEM (2 * STAGE_ELEMS * 2) // 147456 bytes

__global__ __launch_bounds__(256) void gemm_tc(
    const float* __restrict__ bias,
    float* __restrict__ out)            // [T, B, H]
{
    extern __shared__ __nv_bfloat16 sg[];
    const uint32_t sb = (uint32_t)__cvta_generic_to_shared(sg);
    const int tid  = threadIdx.x;
    const int wid  = tid >> 5;
    const int lane = tid & 31;
    const int bn0  = blockIdx.x * 128;
    const int bm0  = blockIdx.y * 128;
    const int wm   = wid & 3;           // m warp-tile (32 rows)
    const int wn   = wid >> 2;          // n warp-tile (64 cols)
    const int grp  = lane >> 2;
    const int tig  = lane & 3;

    // staging granules: g = tid + i*256 -> row = g>>3, gc = g&7 (16B each)
    const int s_row = tid >> 3;         // + 32*i
    const int s_gc  = tid & 7;

    float acc[2][8][4];
#pragma unroll
    for (int mt = 0; mt < 2; mt++)
#pragma unroll
        for (int nt = 0; nt < 8; nt++)
#pragma unroll
            for (int j = 0; j < 4; j++) acc[mt][nt][j] = 0.0f;

#define STAGEC(c, buf)                                                         \
    do {                                                                       \
        const int k0s = (c) * KC;                                              \
        const uint32_t dbase = sb + (uint32_t)(buf) * (STAGE_ELEMS * 2);       \
        _Pragma("unroll")                                                      \
        for (int i = 0; i < 4; i++) {                                          \
            int row = s_row + (i << 5);                                        \
            uint32_t doff = (uint32_t)(row * 144 + s_gc * 16);                 \
            size_t axoff = (size_t)(bm0 + row) * Hn + k0s + s_gc * 8;          \
            size_t bxoff = (size_t)(bn0 + row) * Hn + k0s + s_gc * 8;          \
            cp16(dbase + doff,                      g_Xhi + axoff);            \
            cp16(dbase + ATILE * 2 + doff,          g_Xlo + axoff);            \
            cp16(dbase + ATILE * 4 + doff,          g_Wth + bxoff);            \
            cp16(dbase + ATILE * 6 + doff,          g_Wtl + bxoff);            \
        }                                                                      \
        CP_COMMIT();                                                           \
    } while (0)

    STAGEC(0, 0);

    for (int c = 0; c < 8; c++) {
        if (c < 7) STAGEC(c + 1, (c + 1) & 1);
        if (c < 7) { CP_WAIT(1); } else { CP_WAIT(0); }
        __syncthreads();

        const __nv_bfloat16* Sb = sg + (c & 1) * STAGE_ELEMS;
        const __nv_bfloat16* Ah = Sb;
        const __nv_bfloat16* Al = Sb + ATILE;
        const __nv_bfloat16* Bh = Sb + 2 * ATILE;
        const __nv_bfloat16* Bl = Sb + 3 * ATILE;

#pragma unroll
        for (int ks = 0; ks < 4; ks++) {
            const int kk = ks * 16 + 2 * tig;
            uint32_t ah[2][4], al[2][4], bh[8][2], bl[8][2];
#pragma unroll
            for (int mt = 0; mt < 2; mt++) {
                int base = (wm * 32 + mt * 16 + grp) * KPAD + kk;
                ah[mt][0] = *(const uint32_t*)(Ah + base);
                ah[mt][1] = *(const uint32_t*)(Ah + base + 8 * KPAD);
                ah[mt][2] = *(const uint32_t*)(Ah + base + 8);
                ah[mt][3] = *(const uint32_t*)(Ah + base + 8 * KPAD + 8);
                al[mt][0] = *(const uint32_t*)(Al + base);
                al[mt][1] = *(const uint32_t*)(Al + base + 8 * KPAD);
                al[mt][2] = *(const uint32_t*)(Al + base + 8);
                al[mt][3] = *(const uint32_t*)(Al + base + 8 * KPAD + 8);
            }
#pragma unroll
            for (int nt = 0; nt < 8; nt++) {
                int nb = (wn * 64 + nt * 8 + grp) * KPAD + kk;
                bh[nt][0] = *(const uint32_t*)(Bh + nb);
                bh[nt][1] = *(const uint32_t*)(Bh + nb + 8);
                bl[nt][0] = *(const uint32_t*)(Bl + nb);
                bl[nt][1] = *(const uint32_t*)(Bl + nb + 8);
            }
#pragma unroll
            for (int mt = 0; mt < 2; mt++)
#pragma unroll
                for (int nt = 0; nt < 8; nt++) {
                    MMA_BF16(acc[mt][nt], ah[mt], bh[nt]);
                    MMA_BF16(acc[mt][nt], ah[mt], bl[nt]);
                    MMA_BF16(acc[mt][nt], al[mt], bh[nt]);
                }
        }
        __syncthreads();
    }

    // ---- epilogue: add bias, decode (t, b), store float2 per frag row ----
#pragma unroll
    for (int mt = 0; mt < 2; mt++) {
        const int m0 = bm0 + wm * 32 + mt * 16 + grp;
#pragma unroll
        for (int h = 0; h < 2; h++) {
            const int m  = m0 + 8 * h;
            const int gb = m >> 10;            // T = 1024
            const int tt = m & 1023;
            float* dst = out + ((size_t)tt * Bn + gb) * Hn;
#pragma unroll
            for (int nt = 0; nt < 8; nt++) {
                const int cb = bn0 + wn * 64 + nt * 8 + 2 * tig;
                float2 v;
                v.x = acc[mt][nt][2 * h + 0] + bias[cb];
                v.y = acc[mt][nt][2 * h + 1] + bias[cb + 1];
                *(float2*)(dst + cb) = v;
            }
        }
    }
}

// ===========================================================================
// Phase 2: persistent RNN — EXACT proven-4456 configuration.
// ===========================================================================
#define SWSTR 36
#define SW_FLOATS (8 * SWSTR)
#define PSQ 544
#define RNN_SMEM_BYTES ((16 * SW_FLOATS + 16 * PSQ) * 4)   // 53248

__global__ __launch_bounds__(512) void rnn_steps(
    const float* __restrict__ state0,  // [B, H]
    const float* __restrict__ Wh,      // [H, H]
    float* __restrict__ out)           // [T, B, H] (holds pre on entry)
{
    extern __shared__ float sm[];
    float* SwA = sm;
    float* Ps  = sm + 16 * SW_FLOATS;

    const int tid  = threadIdx.x;
    const int w    = tid >> 5;
    const int lane = tid & 31;
    const int cg   = blockIdx.x & 7;
    const int rg   = blockIdx.x >> 3;
    const int c0   = cg * 64;
    const int r0   = rg * 8;

    const int gc = c0 + lane * 2;
    unsigned long long w2a[16], w2b[16];
    {
        const float* wb = Wh + (size_t)(w * 32) * Hn + gc;
#pragma unroll
        for (int j = 0; j < 16; j++) {
            float a0 = wb[(2 * j) * Hn];
            float a1 = wb[(2 * j + 1) * Hn];
            float b0 = wb[(2 * j) * Hn + 1];
            float b1 = wb[(2 * j + 1) * Hn + 1];
            PACK2(w2a[j], a0, a1);
            PACK2(w2b[j], b0, b1);
        }
    }

    const int rr = tid >> 6;
    const int cc = tid & 63;
    float* opbase = out + (size_t)(r0 + rr) * Hn + c0 + cc;

    const int sr  = lane >> 3;
    const int sk4 = (lane & 7) << 2;

    float* Sw = SwA + w * SW_FLOATS;
    unsigned* cnt = &g_cnt[rg * 1024];

    for (int t = 0; t < Tn; t++) {
        float* op = opbase + (size_t)t * (Bn * Hn);
        float pre = __ldcg(op);

        if (t > 0) {
            while (ld_acq(&cnt[t - 1]) < 8u) { }
        }

        const float* prev = (t == 0) ? state0
                                     : (out + (size_t)(t - 1) * (Bn * Hn));
        {
            const float* pk = prev + (size_t)r0 * Hn + w * 32 + sk4;
            float4 v0 = __ldcg((const float4*)(pk + (size_t)sr * Hn));
            float4 v1 = __ldcg((const float4*)(pk + (size_t)(sr + 4) * Hn));
            *(float4*)(Sw + sr * SWSTR + sk4)       = v0;
            *(float4*)(Sw + (sr + 4) * SWSTR + sk4) = v1;
        }
        __syncwarp();

        unsigned long long acc[8][2];
#pragma unroll
        for (int r = 0; r < 8; r++) { acc[r][0] = 0ull; acc[r][1] = 0ull; }
#pragma unroll
        for (int jj = 0; jj < 8; jj++) {
            const int k = jj * 4;
#pragma unroll
            for (int r = 0; r < 8; r++) {
                ulonglong2 sv = *(const ulonglong2*)(Sw + r * SWSTR + k);
                FMA2(acc[r][0], sv.x, w2a[2 * jj]);
                FMA2(acc[r][0], sv.y, w2a[2 * jj + 1]);
                FMA2(acc[r][1], sv.x, w2b[2 * jj]);
                FMA2(acc[r][1], sv.y, w2b[2 * jj + 1]);
            }
        }

        {
            float* pb = Ps + w * PSQ + lane * 2;
#pragma unroll
            for (int r = 0; r < 8; r++) {
                UF2 u0, u1;
                u0.u = acc[r][0];
                u1.u = acc[r][1];
                float2 p;
                p.x = u0.f.x + u0.f.y;
                p.y = u1.f.x + u1.f.y;
                *(float2*)(pb + r * 68) = p;
            }
        }
        __syncthreads();

        {
            const float* pp = Ps + rr * 68 + cc;
            float s = 0.0f;
#pragma unroll
            for (int q = 0; q < 16; q++) s += pp[q * PSQ];
            __stcg(op, tanhf(pre + s));
        }
        __syncthreads();

        if (t != Tn - 1 && tid == 0) {
            __threadfence();
            atomicAdd(&cnt[t], 1u);
        }
    }
}

extern "C" void kernel_launch(void* const* d_in, const int* in_sizes, int n_in,
                              void* d_out, int out_size)
{
    const float* X    = (const float*)d_in[0];  // inputs_tensor [B,T,H]
    const float* S0   = (const float*)d_in[1];  // state_tensor  [1,B,H]
    const float* Wx   = (const float*)d_in[2];  // [H,H]
    const float* Wh   = (const float*)d_in[3];  // [H,H]
    const float* bias = (const float*)d_in[4];  // [H]
    float* out = (float*)d_out;                 // [T,B,H]

    (void)in_sizes; (void)n_in; (void)out_size;

    cudaFuncSetAttribute(gemm_tc,
                         cudaFuncAttributeMaxDynamicSharedMemorySize,
                         GEMM_SMEM);
    cudaFuncSetAttribute(rnn_steps,
                         cudaFuncAttributeMaxDynamicSharedMemorySize,
                         RNN_SMEM_BYTES);

    zero_cnt<<<32, 512>>>();
    pack_x<<<65536, 256>>>(X);          // 16.7M float4s
    pack_wt<<<1024, 256>>>(Wx);

    dim3 g1(Hn / 128, (Bn * Tn) / 128); // (4, 1024)
    gemm_tc<<<g1, 256, GEMM_SMEM>>>(bias, out);

    rnn_steps<<<128, 512, RNN_SMEM_BYTES>>>(S0, Wh, out);
}